// round 3
// baseline (speedup 1.0000x reference)
#include <cuda_runtime.h>
#include <math.h>

#define MAX_N     16
#define NBINS     4096
#define CAND_MAX  4096
#define BT_MAX    16384
#define H_THREADS 512
#define H_BPB     18
#define C_THREADS 1024
#define C_BPB     18

__device__ unsigned int       g_hist[MAX_N * NBINS];
__device__ unsigned int       g_subhist[MAX_N * NBINS];
__device__ int                g_count[MAX_N];     // # strictly above bin T (< k)
__device__ int                g_btcount[MAX_N];   // # in bin T
__device__ int                g_T[MAX_N];
__device__ int                g_S[MAX_N];
__device__ unsigned int       g_done1[MAX_N];
__device__ unsigned int       g_done2[MAX_N];
__device__ unsigned long long g_cand[MAX_N * CAND_MAX];
__device__ unsigned long long g_binT[MAX_N * BT_MAX];

__device__ __forceinline__ unsigned int mono_f32(float f) {
    unsigned int u = __float_as_uint(f);
    return (u & 0x80000000u) ? ~u : (u | 0x80000000u);
}
__device__ __forceinline__ float inv_mono(unsigned int m) {
    unsigned int u = (m & 0x80000000u) ? (m & 0x7FFFFFFFu) : ~m;
    return __uint_as_float(u);
}
__device__ __forceinline__ unsigned long long umax64(unsigned long long a, unsigned long long b) { return a > b ? a : b; }
__device__ __forceinline__ unsigned long long umin64(unsigned long long a, unsigned long long b) { return a < b ? a : b; }

// warp-aggregated shared-hist add
__device__ __forceinline__ void hist_add(unsigned int* sh, unsigned int bin) {
    unsigned int act = __activemask();
    unsigned int mm = __match_any_sync(act, bin);
    int leader = __ffs(mm) - 1;
    if ((int)(threadIdx.x & 31) == leader) atomicAdd(&sh[bin], (unsigned int)__popc(mm));
}

// ---------------------------------------------------------------------------
// Kernel 1: hist sweep; last block per batch computes threshold bin T and S,
// then zeroes hist/subhist/counters for this replay + the next.
// grid (H_BPB, N), block H_THREADS
// ---------------------------------------------------------------------------
__global__ void hist_thresh_kernel(const float* __restrict__ scores, int A, int k) {
    __shared__ unsigned int sh[NBINS];
    __shared__ unsigned int tmp[H_THREADS];
    __shared__ bool s_last;
    const int b = blockIdx.y;
    const int t = threadIdx.x;

    for (int i = t; i < NBINS; i += H_THREADS) sh[i] = 0;
    __syncthreads();

    const size_t base = (size_t)b * (size_t)A;
    if ((A & 3) == 0) {
        const float4* s4 = (const float4*)(scores + base);
        const int A4 = A >> 2;
        for (int i = blockIdx.x * H_THREADS + t; i < A4; i += H_BPB * H_THREADS) {
            float4 v = s4[i];
            hist_add(sh, mono_f32(v.x) >> 20);
            hist_add(sh, mono_f32(v.y) >> 20);
            hist_add(sh, mono_f32(v.z) >> 20);
            hist_add(sh, mono_f32(v.w) >> 20);
        }
    } else {
        for (int i = blockIdx.x * H_THREADS + t; i < A; i += H_BPB * H_THREADS)
            hist_add(sh, mono_f32(scores[base + i]) >> 20);
    }
    __syncthreads();
    for (int i = t; i < NBINS; i += H_THREADS) {
        unsigned int c = sh[i];
        if (c) atomicAdd(&g_hist[b * NBINS + i], c);
    }
    __threadfence();
    __syncthreads();
    if (t == 0) s_last = (atomicAdd(&g_done1[b], 1u) == (unsigned)gridDim.x - 1u);
    __syncthreads();
    if (!s_last) return;

    // ---- finisher: threshold from full histogram ----
    if (t == 0) g_done1[b] = 0;
    for (int i = t; i < NBINS; i += H_THREADS) sh[i] = g_hist[b * NBINS + i];
    __syncthreads();

    unsigned int seg = 0;
#pragma unroll
    for (int j = 0; j < 8; j++) seg += sh[t * 8 + j];
    tmp[t] = seg;
    __syncthreads();
    for (int d = 1; d < H_THREADS; d <<= 1) {
        unsigned int v = (t + d < H_THREADS) ? tmp[t + d] : 0u;
        __syncthreads();
        tmp[t] += v;
        __syncthreads();
    }
    unsigned int sufMine = tmp[t];
    unsigned int sufNext = (t + 1 < H_THREADS) ? tmp[t + 1] : 0u;
    if (sufMine >= (unsigned)k && sufNext < (unsigned)k) {
        unsigned int acc = sufNext;
        for (int j = 7; j >= 0; j--) {
            unsigned int c = sh[t * 8 + j];
            if (acc + c >= (unsigned)k) { g_T[b] = t * 8 + j; g_S[b] = (int)acc; break; }
            acc += c;
        }
    }
    // zero state for this replay's compact + next replay's hist
    for (int i = t; i < NBINS; i += H_THREADS) {
        g_hist[b * NBINS + i] = 0;
        g_subhist[b * NBINS + i] = 0;
    }
    if (t == 0) { g_count[b] = 0; g_btcount[b] = 0; }
}

// ---------------------------------------------------------------------------
// decode one candidate key -> output row
// ---------------------------------------------------------------------------
__device__ __forceinline__ void decode_write(unsigned long long key,
                                             const float* __restrict__ anchors,
                                             const float* __restrict__ breg,
                                             float* __restrict__ out,
                                             size_t base, int b, int rank, int k) {
    const float CLIP = 4.135166556742356f;  // log(1000/16)
    unsigned int idx = 0xFFFFFFFFu - (unsigned int)(key & 0xFFFFFFFFull);
    float sc = inv_mono((unsigned int)(key >> 32));
    size_t g4 = (base + (size_t)idx) * 4;

    float4 box = *(const float4*)(anchors + g4);
    float4 rc  = *(const float4*)(breg + g4);

    float w  = box.z - box.x + 1.0f;
    float h  = box.w - box.y + 1.0f;
    float cx = box.x + 0.5f * w;
    float cy = box.y + 0.5f * h;

    float dw = fminf(rc.z, CLIP);
    float dh = fminf(rc.w, CLIP);

    float pcx = rc.x * w + cx;
    float pcy = rc.y * h + cy;
    float pw  = expf(dw) * w;
    float ph  = expf(dh) * h;

    float* o = out + ((size_t)b * k + rank) * 5;
    o[0] = pcx - 0.5f * pw;
    o[1] = pcy - 0.5f * ph;
    o[2] = pcx + 0.5f * pw - 1.0f;
    o[3] = pcy + 0.5f * ph - 1.0f;
    o[4] = sc;
}

__device__ __forceinline__ void compact_one(unsigned int m, unsigned int off,
                                            int b, int T) {
    int bin = (int)(m >> 20);
    if (bin < T) return;
    unsigned long long key = ((unsigned long long)m << 32) |
                             (unsigned long long)(0xFFFFFFFFu - off);
    if (bin > T) {
        int p = atomicAdd(&g_count[b], 1);
        if (p < CAND_MAX) g_cand[b * CAND_MAX + p] = key;
    } else {
        atomicAdd(&g_subhist[b * NBINS + ((m >> 8) & 0xFFFu)], 1u);
        int p = atomicAdd(&g_btcount[b], 1);
        if (p < BT_MAX) g_binT[b * BT_MAX + p] = key;
    }
}

// ---------------------------------------------------------------------------
// Kernel 2: compact sweep; last block per batch refines sub-threshold,
// assembles ~k candidates, sorts (register-hybrid bitonic), decodes, writes.
// grid (C_BPB, N), block C_THREADS, dynsmem 4096*8 bytes
// ---------------------------------------------------------------------------
__global__ void compact_sort_kernel(const float* __restrict__ scores,
                                    const float* __restrict__ anchors,
                                    const float* __restrict__ breg,
                                    float* __restrict__ out,
                                    int A, int k) {
    extern __shared__ unsigned long long s[];
    __shared__ unsigned int tmp[C_THREADS];
    __shared__ int sT2, sCnt;
    __shared__ bool s_last;
    const int b = blockIdx.y;
    const int t = threadIdx.x;
    const int T = g_T[b];
    const size_t base = (size_t)b * (size_t)A;

    // ---- compact sweep ----
    if ((A & 3) == 0) {
        const float4* s4 = (const float4*)(scores + base);
        const int A4 = A >> 2;
        for (int i = blockIdx.x * C_THREADS + t; i < A4; i += C_BPB * C_THREADS) {
            float4 v = s4[i];
            unsigned int o = (unsigned int)(i << 2);
            compact_one(mono_f32(v.x), o + 0u, b, T);
            compact_one(mono_f32(v.y), o + 1u, b, T);
            compact_one(mono_f32(v.z), o + 2u, b, T);
            compact_one(mono_f32(v.w), o + 3u, b, T);
        }
    } else {
        for (int i = blockIdx.x * C_THREADS + t; i < A; i += C_BPB * C_THREADS)
            compact_one(mono_f32(scores[base + i]), (unsigned int)i, b, T);
    }
    __threadfence();
    __syncthreads();
    if (t == 0) s_last = (atomicAdd(&g_done2[b], 1u) == (unsigned)gridDim.x - 1u);
    __syncthreads();
    if (!s_last) return;
    if (t == 0) g_done2[b] = 0;

    // ---- Phase A: refined sub-threshold T2 within bin T ----
    unsigned int* shist = (unsigned int*)s;
    for (int i = t; i < NBINS; i += C_THREADS) shist[i] = g_subhist[b * NBINS + i];
    const int S  = g_S[b];
    const int k2 = k - S;
    __syncthreads();

    unsigned int seg = shist[t * 4] + shist[t * 4 + 1] + shist[t * 4 + 2] + shist[t * 4 + 3];
    tmp[t] = seg;
    __syncthreads();
    for (int d = 1; d < C_THREADS; d <<= 1) {
        unsigned int v = (t + d < C_THREADS) ? tmp[t + d] : 0u;
        __syncthreads();
        tmp[t] += v;
        __syncthreads();
    }
    unsigned int sufMine = tmp[t];
    unsigned int sufNext = (t + 1 < C_THREADS) ? tmp[t + 1] : 0u;
    if (sufMine >= (unsigned)k2 && sufNext < (unsigned)k2) {
        unsigned int acc = sufNext;
        for (int j = 3; j >= 0; j--) {
            unsigned int c = shist[t * 4 + j];
            if (acc + c >= (unsigned)k2) { sT2 = t * 4 + j; break; }
            acc += c;
        }
    }
    __syncthreads();
    const int T2 = sT2;
    const int C  = min(g_count[b], CAND_MAX);
    const int BT = min(g_btcount[b], BT_MAX);
    if (t == 0) sCnt = C;
    __syncthreads();   // shist reads done; safe to overwrite s[]

    // ---- Phase B: assemble candidate list ----
    for (int i = t; i < C; i += C_THREADS) s[i] = g_cand[b * CAND_MAX + i];
    for (int i = t; i < BT; i += C_THREADS) {
        unsigned long long key = g_binT[b * BT_MAX + i];
        if ((int)((key >> 40) & 0xFFFull) >= T2) {
            int p = atomicAdd(&sCnt, 1);
            if (p < 4096) s[p] = key;
        }
    }
    __syncthreads();
    int Ct = sCnt; if (Ct > 4096) Ct = 4096;

    if (Ct <= 2048) {
        // ---- Phase C (fast): register-resident hybrid bitonic, P = 2048 ----
        unsigned long long r0 = (t        < Ct) ? s[t]        : 0ull;
        unsigned long long r1 = (t + 1024 < Ct) ? s[t + 1024] : 0ull;

        for (unsigned int kk = 2; kk <= 2048u; kk <<= 1) {
            for (unsigned int jj = kk >> 1; jj >= 32u; jj >>= 1) {
                if (jj == 1024u) {
                    // partner is the thread's own other register (i0=t lower)
                    bool d = ((t & kk) == 0);
                    unsigned long long mx = umax64(r0, r1), mn = umin64(r0, r1);
                    r0 = d ? mx : mn; r1 = d ? mn : mx;
                } else {
                    s[t] = r0; s[t + 1024] = r1;
                    __syncthreads();
                    unsigned long long p0 = s[t ^ jj];
                    unsigned long long p1 = s[(t + 1024) ^ jj];
                    bool l  = ((t & jj) == 0);
                    bool d0 = ((t & kk) == 0);
                    bool d1 = (((t + 1024) & kk) == 0);
                    r0 = (d0 == l) ? umax64(r0, p0) : umin64(r0, p0);
                    r1 = (d1 == l) ? umax64(r1, p1) : umin64(r1, p1);
                    __syncthreads();
                }
            }
            unsigned int jtop = (kk >> 1 < 16u) ? (kk >> 1) : 16u;
            for (unsigned int jj = jtop; jj >= 1u; jj >>= 1) {
                unsigned long long p0 = __shfl_xor_sync(0xFFFFFFFFu, r0, jj);
                unsigned long long p1 = __shfl_xor_sync(0xFFFFFFFFu, r1, jj);
                bool l  = ((t & jj) == 0);
                bool d0 = ((t & kk) == 0);
                bool d1 = (((t + 1024) & kk) == 0);
                r0 = (d0 == l) ? umax64(r0, p0) : umin64(r0, p0);
                r1 = (d1 == l) ? umax64(r1, p1) : umin64(r1, p1);
            }
        }
        // ranks: t from r0, t+1024 from r1
        decode_write(r0, anchors, breg, out, base, b, t, k);
        if (t + 1024 < k) decode_write(r1, anchors, breg, out, base, b, t + 1024, k);
    } else {
        // ---- Phase C (fallback): generic smem bitonic up to P=4096 ----
        int P = 2048;
        while (P < Ct) P <<= 1;
        for (int i = t; i < P; i += C_THREADS)
            if (i >= Ct) s[i] = 0ull;
        __syncthreads();
        for (unsigned int kk = 2; kk <= (unsigned int)P; kk <<= 1) {
            for (unsigned int jj = kk >> 1; jj > 0; jj >>= 1) {
                for (unsigned int i = t; i < (unsigned int)P; i += C_THREADS) {
                    unsigned int ixj = i ^ jj;
                    if (ixj > i) {
                        unsigned long long a = s[i], c2 = s[ixj];
                        bool desc = ((i & kk) == 0);
                        if (desc ? (a < c2) : (a > c2)) { s[i] = c2; s[ixj] = a; }
                    }
                }
                __syncthreads();
            }
        }
        for (int i = t; i < k; i += C_THREADS)
            decode_write(s[i], anchors, breg, out, base, b, i, k);
    }
}

// ---------------------------------------------------------------------------
extern "C" void kernel_launch(void* const* d_in, const int* in_sizes, int n_in,
                              void* d_out, int out_size) {
    const float* anchors    = (const float*)d_in[0];
    const float* objectness = (const float*)d_in[1];
    const float* breg       = (const float*)d_in[2];
    float* out = (float*)d_out;

    const int NA = in_sizes[1];
    const int k  = 2000;
    const int N  = out_size / (k * 5);
    const int A  = NA / N;

    dim3 g1(H_BPB, N);
    hist_thresh_kernel<<<g1, H_THREADS>>>(objectness, A, k);

    dim3 g2(C_BPB, N);
    compact_sort_kernel<<<g2, C_THREADS, 4096 * sizeof(unsigned long long)>>>(
        objectness, anchors, breg, out, A, k);
}